// round 12
// baseline (speedup 1.0000x reference)
#include <cuda_runtime.h>
#include <cuda_bf16.h>
#include <cstdint>

// Problem constants
#define BB 4
#define NN 4096
#define CC 64
#define BN (BB * NN)
#define CHUNK 512
#define NCH (NN / CHUNK)          // 8 chunks per batch

#define TARGETF 560.0f
#define MIN_BOXF 5.0f
#define IOU_THRF 0.2f
#define CONF_THRF 0.001f
#define BOX_CONF_THRF 0.01f
#define MAX_WHF 4096.0f

#define CAP 256                    // per-class member cap for fast path
#define WSTRIDE 8                  // mask words per row (CAP/32)

// ------------------------- scratch (static device memory) -------------------
__device__ float4 g_cbox[BN];                      // clipped boxes, orig order
__device__ float  g_key[BN];                       // valid ? conf : -1
__device__ __align__(128) unsigned char g_tag[BN]; // valid ? cls : 255
__device__ unsigned long long g_ck[BN];            // sorted key chunks
__device__ float4 g_sbox[BN];                      // boxes in sorted order
__device__ float  g_sconf[BN];                     // conf in sorted order
__device__ __align__(128) unsigned char g_stag[BN];// tags in sorted order

// ------------------------- K1: conf / argmax / clip / valid -----------------
__global__ void k1_prepare(const float* __restrict__ boxes,
                           const float* __restrict__ scores,
                           const float* __restrict__ preds) {
    int box  = (blockIdx.x * blockDim.x + threadIdx.x) >> 5;
    int lane = threadIdx.x & 31;
    if (box >= BN) return;

    const float* p = preds + (size_t)box * CC;
    float s = scores[box];

    float v0 = __fmul_rn(p[lane], s);
    float v1 = __fmul_rn(p[lane + 32], s);
    float bv; int bi;
    if (v1 > v0) { bv = v1; bi = lane + 32; } else { bv = v0; bi = lane; }

    #pragma unroll
    for (int o = 16; o > 0; o >>= 1) {
        float ov = __shfl_down_sync(0xffffffffu, bv, o);
        int   oi = __shfl_down_sync(0xffffffffu, bi, o);
        if (ov > bv || (ov == bv && oi < bi)) { bv = ov; bi = oi; }
    }

    if (lane == 0) {
        float4 bx = reinterpret_cast<const float4*>(boxes)[box];
        float x1 = fminf(fmaxf(bx.x, 0.0f), TARGETF);
        float y1 = fminf(fmaxf(bx.y, 0.0f), TARGETF);
        float x2 = fminf(fmaxf(bx.z, 0.0f), TARGETF);
        float y2 = fminf(fmaxf(bx.w, 0.0f), TARGETF);
        float w = __fsub_rn(x2, x1);
        float h = __fsub_rn(y2, y1);
        int valid = (s > BOX_CONF_THRF) && (w > MIN_BOXF) && (h > MIN_BOXF)
                    && (bv > CONF_THRF);
        g_cbox[box] = make_float4(x1, y1, x2, y2);
        g_key[box]  = valid ? bv : -1.0f;
        g_tag[box]  = valid ? (unsigned char)bi : (unsigned char)255;
    }
}

// ------------------------- register bitonic helpers -------------------------
__device__ __forceinline__ unsigned long long kmin(unsigned long long a,
                                                   unsigned long long b) {
    return a < b ? a : b;
}
__device__ __forceinline__ unsigned long long kmax(unsigned long long a,
                                                   unsigned long long b) {
    return a > b ? a : b;
}
__device__ __forceinline__ void stage_j(unsigned long long v[4], int i0,
                                        int lane, int k, int j) {
    if (j >= 4) {
        int m = j >> 2;
        #pragma unroll
        for (int r = 0; r < 4; r++) {
            unsigned long long other = __shfl_xor_sync(0xffffffffu, v[r], m);
            bool up = (((i0 + r) & k) == 0);
            bool keepmin = (((lane & m) == 0) == up);
            v[r] = keepmin ? kmin(v[r], other) : kmax(v[r], other);
        }
    } else if (j == 2) {
        #pragma unroll
        for (int r = 0; r < 2; r++) {
            bool up = (((i0 + r) & k) == 0);
            unsigned long long a = v[r], c = v[r + 2];
            if ((a > c) == up) { v[r] = c; v[r + 2] = a; }
        }
    } else {
        #pragma unroll
        for (int r = 0; r < 4; r += 2) {
            bool up = (((i0 + r) & k) == 0);
            unsigned long long a = v[r], c = v[r + 1];
            if ((a > c) == up) { v[r] = c; v[r + 1] = a; }
        }
    }
}

// ------------------------- K2a: chunk sort (512 keys/block) -----------------
__global__ void __launch_bounds__(128) k2a_chunksort() {
    int b  = blockIdx.x >> 3;
    int ch = blockIdx.x & 7;
    __shared__ unsigned long long sk[CHUNK];
    int tid  = threadIdx.x;
    int lane = tid & 31;
    int i0   = ((tid >> 5) << 7) + (lane << 2);

    #pragma unroll
    for (int u = 0; u < 4; u++) {
        int i   = tid + u * 128;
        int idx = ch * CHUNK + i;
        unsigned int x = __float_as_uint(g_key[b * NN + idx]);
        x = (x & 0x80000000u) ? ~x : (x | 0x80000000u);
        sk[i] = ((unsigned long long)(~x) << 32) | (unsigned int)idx;
    }
    __syncthreads();

    {
        unsigned long long v[4];
        #pragma unroll
        for (int r = 0; r < 4; r++) v[r] = sk[i0 + r];
        #pragma unroll
        for (int k = 2; k <= 128; k <<= 1)
            for (int j = k >> 1; j >= 1; j >>= 1)
                stage_j(v, i0, lane, k, j);
        #pragma unroll
        for (int r = 0; r < 4; r++) sk[i0 + r] = v[r];
    }
    __syncthreads();

    #pragma unroll
    for (int k = 256; k <= CHUNK; k <<= 1) {
        for (int j = k >> 1; j >= 128; j >>= 1) {
            #pragma unroll 2
            for (int u = 0; u < 2; u++) {
                int p   = tid + u * 128;
                int i   = ((p & ~(j - 1)) << 1) | (p & (j - 1));
                int ixj = i | j;
                bool up = ((i & k) == 0);
                unsigned long long a = sk[i], c = sk[ixj];
                if ((a > c) == up) { sk[i] = c; sk[ixj] = a; }
            }
            __syncthreads();
        }
        {
            unsigned long long v[4];
            #pragma unroll
            for (int r = 0; r < 4; r++) v[r] = sk[i0 + r];
            #pragma unroll
            for (int j = 64; j >= 1; j >>= 1)
                stage_j(v, i0, lane, k, j);
            #pragma unroll
            for (int r = 0; r < 4; r++) sk[i0 + r] = v[r];
        }
        __syncthreads();
    }

    #pragma unroll
    for (int u = 0; u < 4; u++) {
        int i = tid + u * 128;
        g_ck[b * NN + ch * CHUNK + i] = sk[i];
    }
}

// ------------------------- K2m: smem rank-merge + scatter + zero-out --------
__global__ void __launch_bounds__(CHUNK) k2m_merge(float* __restrict__ out) {
    int b  = blockIdx.x >> 3;
    int ch = blockIdx.x & 7;
    int tid = threadIdx.x;

    __shared__ unsigned long long sck[NN];          // 32KB
    const unsigned long long* ck = g_ck + b * NN;
    #pragma unroll
    for (int u = 0; u < NCH; u++) sck[tid + u * CHUNK] = ck[tid + u * CHUNK];
    __syncthreads();

    unsigned long long K = sck[ch * CHUNK + tid];
    int rank = tid;

    int lo[NCH], hi[NCH];
    #pragma unroll
    for (int c2 = 0; c2 < NCH; c2++) { lo[c2] = 0; hi[c2] = (c2 == ch) ? 0 : CHUNK; }

    #pragma unroll
    for (int it = 0; it < 10; it++) {
        #pragma unroll
        for (int c2 = 0; c2 < NCH; c2++) {
            if (lo[c2] < hi[c2]) {
                int mid = (lo[c2] + hi[c2]) >> 1;
                unsigned long long v = sck[c2 * CHUNK + mid];
                if (v < K) lo[c2] = mid + 1; else hi[c2] = mid;
            }
        }
    }
    #pragma unroll
    for (int c2 = 0; c2 < NCH; c2++) rank += lo[c2];

    int idx = (int)(K & 0xffffffffull);
    int d = b * NN + rank;
    int s = b * NN + idx;

    float* o = out + (size_t)d * 6;
    o[0] = 0.0f; o[1] = 0.0f; o[2] = 0.0f;
    o[3] = 0.0f; o[4] = 0.0f; o[5] = 0.0f;

    g_sbox[d] = g_cbox[s];
    g_stag[d] = g_tag[s];
    unsigned int up = ~(unsigned int)(K >> 32);
    unsigned int u  = (up & 0x80000000u) ? (up & 0x7fffffffu) : ~up;
    g_sconf[d] = __uint_as_float(u);
}

// movmskb: 1 bit per byte (bit0 of each byte of y) packed into low nibble
__device__ __forceinline__ unsigned int movmsk4(unsigned int eqw) {
    return (((eqw & 0x01010101u) * 0x01020408u) >> 24) & 0xFu;
}

// ------------------------- K3: per-(batch,class) NMS on sorted arrays -------
// 256 threads. Branch-light compaction (movmsk + ffs over set bits) ->
// bit-matrix (upper-triangle words) -> warp-cooperative ffs greedy ->
// direct output writes.
__global__ void __launch_bounds__(256) k3_nms(float* __restrict__ out) {
    int bc   = blockIdx.x;
    int b    = bc >> 6;
    int c    = bc & 63;
    int t    = threadIdx.x;
    int lane = t & 31;
    int wid  = t >> 5;

    __shared__ float sx1[CAP], sy1[CAP], sx2[CAP], sy2[CAP];  // 4KB
    __shared__ float sar[CAP], scf[CAP];                      // 2KB
    __shared__ int   spos[CAP];                               // 1KB
    __shared__ unsigned int smask[CAP * WSTRIDE];             // 8KB
    __shared__ int   flist[CAP];                              // 1KB
    __shared__ unsigned short mb[256];                        // membership bitmap
    __shared__ unsigned short supb[256];                      // fallback suppress
    __shared__ int   warp_tot[9];
    __shared__ unsigned int keepw[WSTRIDE];

    // ---- Stage 1: branch-light compaction over SORTED tags (16/thread) ----
    const uint4* tw = reinterpret_cast<const uint4*>(g_stag + b * NN);
    uint4 wa = tw[t];
    unsigned int cls4 = (unsigned int)c * 0x01010101u;
    unsigned int mbv =
          movmsk4(__vcmpeq4(wa.x, cls4))
        | (movmsk4(__vcmpeq4(wa.y, cls4)) << 4)
        | (movmsk4(__vcmpeq4(wa.z, cls4)) << 8)
        | (movmsk4(__vcmpeq4(wa.w, cls4)) << 12);
    mb[t] = (unsigned short)mbv;
    int cnt = __popc(mbv);

    int inc = cnt;
    #pragma unroll
    for (int o = 1; o < 32; o <<= 1) {
        int tmp = __shfl_up_sync(0xffffffffu, inc, o);
        if (lane >= o) inc += tmp;
    }
    if (lane == 31) warp_tot[wid] = inc;
    __syncthreads();
    if (t == 0) {
        int run = 0;
        #pragma unroll
        for (int w = 0; w < 8; w++) { int v = warp_tot[w]; warp_tot[w] = run; run += v; }
        warp_tot[8] = run;
    }
    __syncthreads();
    int off = (inc - cnt) + warp_tot[wid];
    int base = t * 16;
    unsigned int r = mbv;
    while (r) {                           // expected 0.24 iterations/thread
        int q = __ffs(r) - 1;
        if (off < CAP) flist[off] = base + q;
        off++;
        r &= r - 1;
    }
    __syncthreads();
    int M = warp_tot[8];
    if (M == 0) return;

    float offc = (float)c * MAX_WHF;   // exact in fp32

    if (M <= CAP) {
        // ---- Stage 2: gather member boxes (already in NMS order) ----
        for (int m = t; m < M; m += 256) {
            int pos = flist[m];
            spos[m] = pos;
            scf[m]  = g_sconf[b * NN + pos];
            float4 bx = g_sbox[b * NN + pos];
            sx1[m] = bx.x; sy1[m] = bx.y; sx2[m] = bx.z; sy2[m] = bx.w;
            float ox1 = __fadd_rn(bx.x, offc), oy1 = __fadd_rn(bx.y, offc);
            float ox2 = __fadd_rn(bx.z, offc), oy2 = __fadd_rn(bx.w, offc);
            sar[m] = __fmul_rn(__fsub_rn(ox2, ox1), __fsub_rn(oy2, oy1));
        }
        __syncthreads();

        // ---- Stage 3: pairwise IoU>thr bit-matrix (upper-triangle words) ----
        int W = (M + 31) >> 5;
        for (int i = wid; i < M; i += 8) {
            float ix1 = __fadd_rn(sx1[i], offc), iy1 = __fadd_rn(sy1[i], offc);
            float ix2 = __fadd_rn(sx2[i], offc), iy2 = __fadd_rn(sy2[i], offc);
            float ai  = sar[i];
            for (int cw = (i >> 5); cw < W; cw++) {
                int j = cw * 32 + lane;
                bool s = false;
                if (j < M && j > i) {
                    float jx1 = __fadd_rn(sx1[j], offc), jy1 = __fadd_rn(sy1[j], offc);
                    float jx2 = __fadd_rn(sx2[j], offc), jy2 = __fadd_rn(sy2[j], offc);
                    float aj  = sar[j];
                    float ltx = fmaxf(ix1, jx1), lty = fmaxf(iy1, jy1);
                    float rbx = fminf(ix2, jx2), rby = fminf(iy2, jy2);
                    float w = fmaxf(__fsub_rn(rbx, ltx), 0.0f);
                    float h = fmaxf(__fsub_rn(rby, lty), 0.0f);
                    float inter = __fmul_rn(w, h);
                    float denom = __fadd_rn(__fsub_rn(__fadd_rn(ai, aj), inter), 1e-9f);
                    s = __fdiv_rn(inter, denom) > IOU_THRF;
                }
                unsigned int bal = __ballot_sync(0xffffffffu, s);
                if (lane == 0) smask[i * WSTRIDE + cw] = bal;
            }
        }
        __syncthreads();

        // ---- Stage 4a: warp-cooperative ffs greedy (warp 0) ----
        if (wid == 0) {
            int W2 = (M + 31) >> 5;
            unsigned int rem = 0;
            if (lane < W2) {
                int rb = M - lane * 32;
                rem = (rb >= 32) ? 0xffffffffu : ((1u << rb) - 1u);
            }
            unsigned int keep = 0;
            for (;;) {
                unsigned int bal = __ballot_sync(0xffffffffu, rem != 0);
                if (!bal) break;
                int src = __ffs(bal) - 1;
                unsigned int word = __shfl_sync(0xffffffffu, rem, src);
                int i = (src << 5) + __ffs(word) - 1;
                if (lane == src) {
                    keep |= 1u << (i & 31);
                    rem  &= ~(1u << (i & 31));
                }
                unsigned int supr = (lane < W2 && lane >= (i >> 5))
                                  ? smask[i * WSTRIDE + lane] : 0u;
                rem &= ~supr;
            }
            if (lane < WSTRIDE) keepw[lane] = (lane < W2) ? keep : 0u;
        }
        __syncthreads();

        // ---- Stage 4b: write kept rows DIRECTLY to output at row spos ----
        for (int m = t; m < M; m += 256) {
            if ((keepw[m >> 5] >> (m & 31)) & 1u) {
                float* o = out + ((size_t)b * NN + spos[m]) * 6;
                o[0] = sx1[m]; o[1] = sy1[m]; o[2] = sx2[m]; o[3] = sy2[m];
                o[4] = scf[m]; o[5] = (float)c;
            }
        }
        return;
    }

    // ---- Fallback (M > CAP): bitmap greedy in position order (never hit) ---
    supb[t] = 0;
    __syncthreads();
    for (int w = 0; w < 256; w++) {
        unsigned int avail = (unsigned int)(mb[w] & (unsigned short)~supb[w]);
        while (avail) {
            int bit = __ffs(avail) - 1;
            int pos = w * 16 + bit;
            float4 bi = g_sbox[b * NN + pos];
            float ix1 = __fadd_rn(bi.x, offc), iy1 = __fadd_rn(bi.y, offc);
            float ix2 = __fadd_rn(bi.z, offc), iy2 = __fadd_rn(bi.w, offc);
            float ai  = __fmul_rn(__fsub_rn(ix2, ix1), __fsub_rn(iy2, iy1));
            if (t == 0) {
                float* o = out + ((size_t)b * NN + pos) * 6;
                o[0] = bi.x; o[1] = bi.y; o[2] = bi.z; o[3] = bi.w;
                o[4] = g_sconf[b * NN + pos];
                o[5] = (float)c;
            }
            unsigned int mymb = mb[t], mysup = supb[t];
            #pragma unroll
            for (int q = 0; q < 16; q++) {
                int j = t * 16 + q;
                if (j > pos && ((mymb >> q) & 1u) && !((mysup >> q) & 1u)) {
                    float4 bj = g_sbox[b * NN + j];
                    float jx1 = __fadd_rn(bj.x, offc), jy1 = __fadd_rn(bj.y, offc);
                    float jx2 = __fadd_rn(bj.z, offc), jy2 = __fadd_rn(bj.w, offc);
                    float aj  = __fmul_rn(__fsub_rn(jx2, jx1), __fsub_rn(jy2, jy1));
                    float ltx = fmaxf(ix1, jx1), lty = fmaxf(iy1, jy1);
                    float rbx = fminf(ix2, jx2), rby = fminf(iy2, jy2);
                    float wq = fmaxf(__fsub_rn(rbx, ltx), 0.0f);
                    float hq = fmaxf(__fsub_rn(rby, lty), 0.0f);
                    float inter = __fmul_rn(wq, hq);
                    float denom = __fadd_rn(__fsub_rn(__fadd_rn(ai, aj), inter), 1e-9f);
                    if (__fdiv_rn(inter, denom) > IOU_THRF) mysup |= 1u << q;
                }
            }
            supb[t] = (unsigned short)mysup;
            __syncthreads();
            avail = (unsigned int)(mb[w] & (unsigned short)~supb[w]);
            avail &= ~((bit == 31) ? 0xffffffffu : ((1u << (bit + 1)) - 1u));
        }
        __syncthreads();
    }
}

// ------------------------- launch -------------------------------------------
extern "C" void kernel_launch(void* const* d_in, const int* in_sizes, int n_in,
                              void* d_out, int out_size) {
    const float *boxes = nullptr, *scores = nullptr, *preds = nullptr;
    for (int i = 0; i < n_in; i++) {
        if (in_sizes[i] == BN * 4)       boxes  = (const float*)d_in[i];
        else if (in_sizes[i] == BN)      scores = (const float*)d_in[i];
        else if (in_sizes[i] == BN * CC) preds  = (const float*)d_in[i];
    }
    float* out = (float*)d_out;

    k1_prepare<<<(BN * 32) / 1024, 1024>>>(boxes, scores, preds);
    k2a_chunksort<<<BB * NCH, 128>>>();
    k2m_merge<<<BB * NCH, CHUNK>>>(out);
    k3_nms<<<BB * CC, 256>>>(out);
}